// round 2
// baseline (speedup 1.0000x reference)
#include <cuda_runtime.h>
#include <cuda_bf16.h>
#include <math.h>

#define BB 2
#define C 256
#define DD 16
#define WW 32
#define HH 32
#define NN (DD*WW*HH)     // 16384 spatial positions
#define SN 256
#define CS 256
#define HEADS 8
#define DH 32
#define EPSV 1e-6f

// ---------------- scratch (device globals; no allocations allowed) ----------
__device__ float g_hn[BB*C*NN];   // normalized x, [b][c][n]
__device__ float g_q [BB*C*NN];   // q projection, [b][c][n]
__device__ float g_ao[BB*C*NN];   // attention out, [b][c][n]
__device__ float g_k [BB*C*SN];   // k, [b][c][s]
__device__ float g_v [BB*C*SN];   // v, [b][c][s]

// ---------------------------------------------------------------------------
// Kernel 1: style path. One block per (b, token). LN over CS, then each
// thread o computes k[b,o,n] and v[b,o,n].
// ---------------------------------------------------------------------------
__global__ void style_kernel(const float* __restrict__ s,
                             const float* __restrict__ lns_w,
                             const float* __restrict__ lns_b,
                             const float* __restrict__ Wk,
                             const float* __restrict__ Wv) {
    int b = blockIdx.x / SN;
    int n = blockIdx.x % SN;
    int t = threadIdx.x;          // 256 threads == CS
    __shared__ float sh[CS];
    __shared__ float ws1[8], ws2[8];
    __shared__ float mu_s, rstd_s;

    const float* srow = s + ((size_t)b*SN + n)*CS;
    float val = srow[t];
    float s1 = val, s2 = val*val;
    #pragma unroll
    for (int o = 16; o > 0; o >>= 1) {
        s1 += __shfl_xor_sync(0xffffffffu, s1, o);
        s2 += __shfl_xor_sync(0xffffffffu, s2, o);
    }
    int lane = t & 31, wid = t >> 5;
    if (lane == 0) { ws1[wid] = s1; ws2[wid] = s2; }
    __syncthreads();
    if (t == 0) {
        float a = 0.f, b2 = 0.f;
        #pragma unroll
        for (int i = 0; i < 8; i++) { a += ws1[i]; b2 += ws2[i]; }
        float mu = a / CS;
        float var = b2 / CS - mu*mu;
        mu_s = mu;
        rstd_s = rsqrtf(var + EPSV);
    }
    __syncthreads();
    sh[t] = (val - mu_s) * rstd_s * lns_w[t] + lns_b[t];
    __syncthreads();

    const float* wkr = Wk + (size_t)t * CS;
    const float* wvr = Wv + (size_t)t * CS;
    float acck = 0.f, accv = 0.f;
    #pragma unroll 8
    for (int c = 0; c < CS; c++) {
        float sv = sh[c];
        acck += wkr[c] * sv;
        accv += wvr[c] * sv;
    }
    g_k[((size_t)b*C + t)*SN + n] = acck;
    g_v[((size_t)b*C + t)*SN + n] = accv;
}

// ---------------------------------------------------------------------------
// Kernel 2: channel LayerNorm of x. One thread per spatial position; loop
// over channels twice (second pass re-reads; hot in L2).
// ---------------------------------------------------------------------------
__global__ void lnx_kernel(const float* __restrict__ x,
                           const float* __restrict__ ln_w,
                           const float* __restrict__ ln_b) {
    __shared__ float wsh[C], bsh[C];
    for (int i = threadIdx.x; i < C; i += blockDim.x) {
        wsh[i] = ln_w[i];
        bsh[i] = ln_b[i];
    }
    __syncthreads();

    int b = blockIdx.y;
    int pos = blockIdx.x * blockDim.x + threadIdx.x;
    const float* xb = x + (size_t)b*C*NN;
    float sum = 0.f, sq = 0.f;
    #pragma unroll 8
    for (int c = 0; c < C; c++) {
        float v = xb[(size_t)c*NN + pos];
        sum += v; sq += v*v;
    }
    float mean = sum * (1.f/C);
    float rstd = rsqrtf(sq * (1.f/C) - mean*mean + EPSV);
    float* hb = g_hn + (size_t)b*C*NN;
    #pragma unroll 8
    for (int c = 0; c < C; c++) {
        float v = xb[(size_t)c*NN + pos];
        hb[(size_t)c*NN + pos] = (v - mean) * rstd * wsh[c] + bsh[c];
    }
}

// ---------------------------------------------------------------------------
// Kernel 3/5: SGEMM  Out[b,o,n] = sum_c A[o,c] * In[b,c,n]  (+bias+residual)
// BM=64 (o), BN=64 (n), BK=16; 256 threads, 4x4 micro-tile per thread.
// ---------------------------------------------------------------------------
template<bool EPILOGUE>
__global__ void gemm_kernel(const float* __restrict__ A,     // [C][C] (o,c)
                            const float* __restrict__ In,    // [B][C][N]
                            float*       __restrict__ Out,   // [B][C][N]
                            const float* __restrict__ bias,  // [C] or null
                            const float* __restrict__ resid) // [B][C][N] or null
{
    __shared__ float As[16][64];   // As[k][m]
    __shared__ float Bs[16][64];   // Bs[k][n]

    int nb = blockIdx.x * 64;
    int om = blockIdx.y * 64;
    int b  = blockIdx.z;
    int tid = threadIdx.x;
    int tn = tid & 15;      // 0..15 -> n
    int tm = tid >> 4;      // 0..15 -> m

    const float* Inb = In + (size_t)b*C*NN;

    float acc[4][4];
    #pragma unroll
    for (int i = 0; i < 4; i++)
        #pragma unroll
        for (int j = 0; j < 4; j++) acc[i][j] = 0.f;

    int am = tid >> 2;            // 0..63
    int aj = (tid & 3) * 4;       // 0,4,8,12
    int bk = tid >> 4;            // 0..15
    int bj = (tid & 15) * 4;      // 0..60

    for (int k0 = 0; k0 < C; k0 += 16) {
        // A tile: 64 rows (o) x 16 cols (c), stored transposed
        float4 av = *(const float4*)(A + (size_t)(om + am)*C + k0 + aj);
        As[aj+0][am] = av.x;
        As[aj+1][am] = av.y;
        As[aj+2][am] = av.z;
        As[aj+3][am] = av.w;
        // B tile: 16 rows (c) x 64 cols (n)
        float4 bv = *(const float4*)(Inb + (size_t)(k0 + bk)*NN + nb + bj);
        *(float4*)&Bs[bk][bj] = bv;
        __syncthreads();

        #pragma unroll
        for (int kk = 0; kk < 16; kk++) {
            float4 a = *(const float4*)&As[kk][tm*4];
            float4 bb = *(const float4*)&Bs[kk][tn*4];
            acc[0][0] += a.x*bb.x; acc[0][1] += a.x*bb.y; acc[0][2] += a.x*bb.z; acc[0][3] += a.x*bb.w;
            acc[1][0] += a.y*bb.x; acc[1][1] += a.y*bb.y; acc[1][2] += a.y*bb.z; acc[1][3] += a.y*bb.w;
            acc[2][0] += a.z*bb.x; acc[2][1] += a.z*bb.y; acc[2][2] += a.z*bb.z; acc[2][3] += a.z*bb.w;
            acc[3][0] += a.w*bb.x; acc[3][1] += a.w*bb.y; acc[3][2] += a.w*bb.z; acc[3][3] += a.w*bb.w;
        }
        __syncthreads();
    }

    #pragma unroll
    for (int i = 0; i < 4; i++) {
        int o = om + tm*4 + i;
        size_t base = ((size_t)b*C + o)*NN + nb + tn*4;
        float4 r;
        r.x = acc[i][0]; r.y = acc[i][1]; r.z = acc[i][2]; r.w = acc[i][3];
        if (EPILOGUE) {
            float bo = bias[o];
            float4 xr = *(const float4*)(resid + base);
            r.x += bo + xr.x; r.y += bo + xr.y; r.z += bo + xr.z; r.w += bo + xr.w;
        }
        *(float4*)(Out + base) = r;
    }
}

// ---------------------------------------------------------------------------
// Kernel 4: attention. grid (N/128, HEADS, B), 128 threads, one position per
// thread. K/V staged in dynamic shared as [s][36] (padded) for float4 reads.
// Online softmax in chunks of 16 tokens.
// ---------------------------------------------------------------------------
#define KV_STRIDE 36
__global__ void attn_kernel() {
    extern __shared__ float smem[];
    float* ksh = smem;                 // SN * KV_STRIDE
    float* vsh = smem + SN*KV_STRIDE;

    int b = blockIdx.z;
    int h = blockIdx.y;
    int pos = blockIdx.x * blockDim.x + threadIdx.x;

    const float* kb = g_k + ((size_t)b*C + h*DH)*SN;   // [d][s]
    const float* vb = g_v + ((size_t)b*C + h*DH)*SN;
    for (int i = threadIdx.x; i < DH*SN; i += blockDim.x) {
        int d = i / SN, sidx = i % SN;
        ksh[sidx*KV_STRIDE + d] = kb[i];
        vsh[sidx*KV_STRIDE + d] = vb[i];
    }
    __syncthreads();

    const float scale = rsqrtf((float)DH);
    float q[DH];
    #pragma unroll
    for (int d = 0; d < DH; d++)
        q[d] = g_q[((size_t)b*C + h*DH + d)*NN + pos] * scale;

    float out[DH];
    #pragma unroll
    for (int d = 0; d < DH; d++) out[d] = 0.f;
    float m = -INFINITY, l = 0.f;

    for (int s0 = 0; s0 < SN; s0 += 16) {
        float sc[16];
        float cmax = -INFINITY;
        #pragma unroll
        for (int j = 0; j < 16; j++) {
            const float* kr = ksh + (s0 + j)*KV_STRIDE;
            float a = 0.f;
            #pragma unroll
            for (int d4 = 0; d4 < DH; d4 += 4) {
                float4 kv = *(const float4*)(kr + d4);
                a += q[d4+0]*kv.x + q[d4+1]*kv.y + q[d4+2]*kv.z + q[d4+3]*kv.w;
            }
            sc[j] = a;
            cmax = fmaxf(cmax, a);
        }
        float newm = fmaxf(m, cmax);
        float corr = __expf(m - newm);
        l *= corr;
        #pragma unroll
        for (int d = 0; d < DH; d++) out[d] *= corr;
        #pragma unroll
        for (int j = 0; j < 16; j++) {
            float p = __expf(sc[j] - newm);
            l += p;
            const float* vr = vsh + (s0 + j)*KV_STRIDE;
            #pragma unroll
            for (int d4 = 0; d4 < DH; d4 += 4) {
                float4 vv = *(const float4*)(vr + d4);
                out[d4+0] += p*vv.x; out[d4+1] += p*vv.y;
                out[d4+2] += p*vv.z; out[d4+3] += p*vv.w;
            }
        }
        m = newm;
    }

    float inv = 1.f / l;
    #pragma unroll
    for (int d = 0; d < DH; d++)
        g_ao[((size_t)b*C + h*DH + d)*NN + pos] = out[d] * inv;
}

// ---------------------------------------------------------------------------
extern "C" void kernel_launch(void* const* d_in, const int* in_sizes, int n_in,
                              void* d_out, int out_size) {
    const float* x     = (const float*)d_in[0];
    const float* s     = (const float*)d_in[1];
    const float* ln_w  = (const float*)d_in[2];
    const float* ln_b  = (const float*)d_in[3];
    const float* lns_w = (const float*)d_in[4];
    const float* lns_b = (const float*)d_in[5];
    const float* Wq    = (const float*)d_in[6];
    const float* Wk    = (const float*)d_in[7];
    const float* Wv    = (const float*)d_in[8];
    const float* Wo    = (const float*)d_in[9];
    const float* bo    = (const float*)d_in[10];
    float* out = (float*)d_out;

    float* hn_p; cudaGetSymbolAddress((void**)&hn_p, g_hn);
    float* q_p;  cudaGetSymbolAddress((void**)&q_p,  g_q);
    float* ao_p; cudaGetSymbolAddress((void**)&ao_p, g_ao);

    // 1: style LN + K/V projections
    style_kernel<<<BB*SN, 256>>>(s, lns_w, lns_b, Wk, Wv);

    // 2: channel LN of x
    {
        dim3 grid(NN/128, BB);
        lnx_kernel<<<grid, 128>>>(x, ln_w, ln_b);
    }

    // 3: Q = Wq @ hn
    {
        dim3 grid(NN/64, C/64, BB);
        gemm_kernel<false><<<grid, 256>>>(Wq, hn_p, q_p, nullptr, nullptr);
    }

    // 4: attention
    {
        int shbytes = 2 * SN * KV_STRIDE * (int)sizeof(float);
        cudaFuncSetAttribute(attn_kernel,
                             cudaFuncAttributeMaxDynamicSharedMemorySize, shbytes);
        dim3 grid(NN/128, HEADS, BB);
        attn_kernel<<<grid, 128, shbytes>>>();
    }

    // 5: out = Wo @ ao + bo + x
    {
        dim3 grid(NN/64, C/64, BB);
        gemm_kernel<true><<<grid, 256>>>(Wo, ao_p, out, bo, x);
    }
}

// round 3
// speedup vs baseline: 1.0018x; 1.0018x over previous
#include <cuda_runtime.h>
#include <cuda_bf16.h>
#include <math.h>

#define BB 2
#define C 256
#define DD 16
#define WW 32
#define HH 32
#define NN (DD*WW*HH)     // 16384 spatial positions
#define SN 256
#define CS 256
#define HEADS 8
#define DH 32
#define EPSV 1e-6f

// ---------------- scratch (device globals; no allocations allowed) ----------
__device__ float g_hn[BB*C*NN];   // normalized x, [b][c][n]
__device__ float g_q [BB*C*NN];   // q projection, [b][c][n]
__device__ float g_ao[BB*C*NN];   // attention out, [b][c][n]
__device__ float g_k [BB*C*SN];   // k, [b][c][s]
__device__ float g_v [BB*C*SN];   // v, [b][c][s]

// ---------------------------------------------------------------------------
// Kernel 1: style path. One block per (b, token). LN over CS, then each
// thread o computes k[b,o,n] and v[b,o,n].
// ---------------------------------------------------------------------------
__global__ void style_kernel(const float* __restrict__ s,
                             const float* __restrict__ lns_w,
                             const float* __restrict__ lns_b,
                             const float* __restrict__ Wk,
                             const float* __restrict__ Wv) {
    int b = blockIdx.x / SN;
    int n = blockIdx.x % SN;
    int t = threadIdx.x;          // 256 threads == CS
    __shared__ float sh[CS];
    __shared__ float ws1[8], ws2[8];
    __shared__ float mu_s, rstd_s;

    const float* srow = s + ((size_t)b*SN + n)*CS;
    float val = srow[t];
    float s1 = val, s2 = val*val;
    #pragma unroll
    for (int o = 16; o > 0; o >>= 1) {
        s1 += __shfl_xor_sync(0xffffffffu, s1, o);
        s2 += __shfl_xor_sync(0xffffffffu, s2, o);
    }
    int lane = t & 31, wid = t >> 5;
    if (lane == 0) { ws1[wid] = s1; ws2[wid] = s2; }
    __syncthreads();
    if (t == 0) {
        float a = 0.f, b2 = 0.f;
        #pragma unroll
        for (int i = 0; i < 8; i++) { a += ws1[i]; b2 += ws2[i]; }
        float mu = a / CS;
        float var = b2 / CS - mu*mu;
        mu_s = mu;
        rstd_s = rsqrtf(var + EPSV);
    }
    __syncthreads();
    sh[t] = (val - mu_s) * rstd_s * lns_w[t] + lns_b[t];
    __syncthreads();

    const float* wkr = Wk + (size_t)t * CS;
    const float* wvr = Wv + (size_t)t * CS;
    float acck = 0.f, accv = 0.f;
    #pragma unroll 8
    for (int c = 0; c < CS; c++) {
        float sv = sh[c];
        acck += wkr[c] * sv;
        accv += wvr[c] * sv;
    }
    g_k[((size_t)b*C + t)*SN + n] = acck;
    g_v[((size_t)b*C + t)*SN + n] = accv;
}

// ---------------------------------------------------------------------------
// Kernel 2: channel LayerNorm of x. One thread per spatial position; loop
// over channels twice (second pass re-reads; hot in L2).
// ---------------------------------------------------------------------------
__global__ void lnx_kernel(const float* __restrict__ x,
                           const float* __restrict__ ln_w,
                           const float* __restrict__ ln_b) {
    __shared__ float wsh[C], bsh[C];
    for (int i = threadIdx.x; i < C; i += blockDim.x) {
        wsh[i] = ln_w[i];
        bsh[i] = ln_b[i];
    }
    __syncthreads();

    int b = blockIdx.y;
    int pos = blockIdx.x * blockDim.x + threadIdx.x;
    const float* xb = x + (size_t)b*C*NN;
    float sum = 0.f, sq = 0.f;
    #pragma unroll 8
    for (int c = 0; c < C; c++) {
        float v = xb[(size_t)c*NN + pos];
        sum += v; sq += v*v;
    }
    float mean = sum * (1.f/C);
    float rstd = rsqrtf(sq * (1.f/C) - mean*mean + EPSV);
    float* hb = g_hn + (size_t)b*C*NN;
    #pragma unroll 8
    for (int c = 0; c < C; c++) {
        float v = xb[(size_t)c*NN + pos];
        hb[(size_t)c*NN + pos] = (v - mean) * rstd * wsh[c] + bsh[c];
    }
}

// ---------------------------------------------------------------------------
// Kernel 3/5: SGEMM  Out[b,o,n] = sum_c A[o,c] * In[b,c,n]  (+bias+residual)
// BM=64 (o), BN=64 (n), BK=16; 256 threads, 4x4 micro-tile per thread.
// ---------------------------------------------------------------------------
template<bool EPILOGUE>
__global__ void gemm_kernel(const float* __restrict__ A,     // [C][C] (o,c)
                            const float* __restrict__ In,    // [B][C][N]
                            float*       __restrict__ Out,   // [B][C][N]
                            const float* __restrict__ bias,  // [C] or null
                            const float* __restrict__ resid) // [B][C][N] or null
{
    __shared__ float As[16][64];   // As[k][m]
    __shared__ float Bs[16][64];   // Bs[k][n]

    int nb = blockIdx.x * 64;
    int om = blockIdx.y * 64;
    int b  = blockIdx.z;
    int tid = threadIdx.x;
    int tn = tid & 15;      // 0..15 -> n
    int tm = tid >> 4;      // 0..15 -> m

    const float* Inb = In + (size_t)b*C*NN;

    float acc[4][4];
    #pragma unroll
    for (int i = 0; i < 4; i++)
        #pragma unroll
        for (int j = 0; j < 4; j++) acc[i][j] = 0.f;

    int am = tid >> 2;            // 0..63
    int aj = (tid & 3) * 4;       // 0,4,8,12
    int bk = tid >> 4;            // 0..15
    int bj = (tid & 15) * 4;      // 0..60

    for (int k0 = 0; k0 < C; k0 += 16) {
        // A tile: 64 rows (o) x 16 cols (c), stored transposed
        float4 av = *(const float4*)(A + (size_t)(om + am)*C + k0 + aj);
        As[aj+0][am] = av.x;
        As[aj+1][am] = av.y;
        As[aj+2][am] = av.z;
        As[aj+3][am] = av.w;
        // B tile: 16 rows (c) x 64 cols (n)
        float4 bv = *(const float4*)(Inb + (size_t)(k0 + bk)*NN + nb + bj);
        *(float4*)&Bs[bk][bj] = bv;
        __syncthreads();

        #pragma unroll
        for (int kk = 0; kk < 16; kk++) {
            float4 a = *(const float4*)&As[kk][tm*4];
            float4 bb = *(const float4*)&Bs[kk][tn*4];
            acc[0][0] += a.x*bb.x; acc[0][1] += a.x*bb.y; acc[0][2] += a.x*bb.z; acc[0][3] += a.x*bb.w;
            acc[1][0] += a.y*bb.x; acc[1][1] += a.y*bb.y; acc[1][2] += a.y*bb.z; acc[1][3] += a.y*bb.w;
            acc[2][0] += a.z*bb.x; acc[2][1] += a.z*bb.y; acc[2][2] += a.z*bb.z; acc[2][3] += a.z*bb.w;
            acc[3][0] += a.w*bb.x; acc[3][1] += a.w*bb.y; acc[3][2] += a.w*bb.z; acc[3][3] += a.w*bb.w;
        }
        __syncthreads();
    }

    #pragma unroll
    for (int i = 0; i < 4; i++) {
        int o = om + tm*4 + i;
        size_t base = ((size_t)b*C + o)*NN + nb + tn*4;
        float4 r;
        r.x = acc[i][0]; r.y = acc[i][1]; r.z = acc[i][2]; r.w = acc[i][3];
        if (EPILOGUE) {
            float bo = bias[o];
            float4 xr = *(const float4*)(resid + base);
            r.x += bo + xr.x; r.y += bo + xr.y; r.z += bo + xr.z; r.w += bo + xr.w;
        }
        *(float4*)(Out + base) = r;
    }
}

// ---------------------------------------------------------------------------
// Kernel 4: attention. grid (N/128, HEADS, B), 128 threads, one position per
// thread. K/V staged in dynamic shared as [s][36] (padded) for float4 reads.
// Online softmax in chunks of 16 tokens.
// ---------------------------------------------------------------------------
#define KV_STRIDE 36
__global__ void attn_kernel() {
    extern __shared__ float smem[];
    float* ksh = smem;                 // SN * KV_STRIDE
    float* vsh = smem + SN*KV_STRIDE;

    int b = blockIdx.z;
    int h = blockIdx.y;
    int pos = blockIdx.x * blockDim.x + threadIdx.x;

    const float* kb = g_k + ((size_t)b*C + h*DH)*SN;   // [d][s]
    const float* vb = g_v + ((size_t)b*C + h*DH)*SN;
    for (int i = threadIdx.x; i < DH*SN; i += blockDim.x) {
        int d = i / SN, sidx = i % SN;
        ksh[sidx*KV_STRIDE + d] = kb[i];
        vsh[sidx*KV_STRIDE + d] = vb[i];
    }
    __syncthreads();

    const float scale = rsqrtf((float)DH);
    float q[DH];
    #pragma unroll
    for (int d = 0; d < DH; d++)
        q[d] = g_q[((size_t)b*C + h*DH + d)*NN + pos] * scale;

    float out[DH];
    #pragma unroll
    for (int d = 0; d < DH; d++) out[d] = 0.f;
    float m = -INFINITY, l = 0.f;

    for (int s0 = 0; s0 < SN; s0 += 16) {
        float sc[16];
        float cmax = -INFINITY;
        #pragma unroll
        for (int j = 0; j < 16; j++) {
            const float* kr = ksh + (s0 + j)*KV_STRIDE;
            float a = 0.f;
            #pragma unroll
            for (int d4 = 0; d4 < DH; d4 += 4) {
                float4 kv = *(const float4*)(kr + d4);
                a += q[d4+0]*kv.x + q[d4+1]*kv.y + q[d4+2]*kv.z + q[d4+3]*kv.w;
            }
            sc[j] = a;
            cmax = fmaxf(cmax, a);
        }
        float newm = fmaxf(m, cmax);
        float corr = __expf(m - newm);
        l *= corr;
        #pragma unroll
        for (int d = 0; d < DH; d++) out[d] *= corr;
        #pragma unroll
        for (int j = 0; j < 16; j++) {
            float p = __expf(sc[j] - newm);
            l += p;
            const float* vr = vsh + (s0 + j)*KV_STRIDE;
            #pragma unroll
            for (int d4 = 0; d4 < DH; d4 += 4) {
                float4 vv = *(const float4*)(vr + d4);
                out[d4+0] += p*vv.x; out[d4+1] += p*vv.y;
                out[d4+2] += p*vv.z; out[d4+3] += p*vv.w;
            }
        }
        m = newm;
    }

    float inv = 1.f / l;
    #pragma unroll
    for (int d = 0; d < DH; d++)
        g_ao[((size_t)b*C + h*DH + d)*NN + pos] = out[d] * inv;
}

// ---------------------------------------------------------------------------
extern "C" void kernel_launch(void* const* d_in, const int* in_sizes, int n_in,
                              void* d_out, int out_size) {
    const float* x     = (const float*)d_in[0];
    const float* s     = (const float*)d_in[1];
    const float* ln_w  = (const float*)d_in[2];
    const float* ln_b  = (const float*)d_in[3];
    const float* lns_w = (const float*)d_in[4];
    const float* lns_b = (const float*)d_in[5];
    const float* Wq    = (const float*)d_in[6];
    const float* Wk    = (const float*)d_in[7];
    const float* Wv    = (const float*)d_in[8];
    const float* Wo    = (const float*)d_in[9];
    const float* bo    = (const float*)d_in[10];
    float* out = (float*)d_out;

    float* hn_p; cudaGetSymbolAddress((void**)&hn_p, g_hn);
    float* q_p;  cudaGetSymbolAddress((void**)&q_p,  g_q);
    float* ao_p; cudaGetSymbolAddress((void**)&ao_p, g_ao);

    // 1: style LN + K/V projections
    style_kernel<<<BB*SN, 256>>>(s, lns_w, lns_b, Wk, Wv);

    // 2: channel LN of x
    {
        dim3 grid(NN/128, BB);
        lnx_kernel<<<grid, 128>>>(x, ln_w, ln_b);
    }

    // 3: Q = Wq @ hn
    {
        dim3 grid(NN/64, C/64, BB);
        gemm_kernel<false><<<grid, 256>>>(Wq, hn_p, q_p, nullptr, nullptr);
    }

    // 4: attention
    {
        int shbytes = 2 * SN * KV_STRIDE * (int)sizeof(float);
        cudaFuncSetAttribute(attn_kernel,
                             cudaFuncAttributeMaxDynamicSharedMemorySize, shbytes);
        dim3 grid(NN/128, HEADS, BB);
        attn_kernel<<<grid, 128, shbytes>>>();
    }

    // 5: out = Wo @ ao + bo + x
    {
        dim3 grid(NN/64, C/64, BB);
        gemm_kernel<true><<<grid, 256>>>(Wo, ao_p, out, bo, x);
    }
}